// round 1
// baseline (speedup 1.0000x reference)
#include <cuda_runtime.h>
#include <cuda_bf16.h>
#include <math.h>

// Problem constants
#define BSZ 4
#define SEQ 512
#define DM 1024
#define NH 16
#define NKV 4
#define NREP 4
#define HD 64
#define NROWS (BSZ*SEQ)          // 2048
#define OUT_ELEMS (BSZ*SEQ*DM)   // 2097152
#define ATTN_ELEMS (BSZ*NH*SEQ*SEQ)

// Scratch (device globals; no runtime allocation allowed)
__device__ float g_xq[NROWS * DM];            // 8 MB   (b*S+i, h*64+d)
__device__ float g_xk[NROWS * (NKV*HD)];      // 2 MB   (b*S+j, kv*64+d)
__device__ float g_xkT[BSZ * NKV * HD * SEQ]; // 2 MB   (b,kv,d,j)
__device__ float g_ws[NROWS * NH * DM / 2 * 2]; // placeholder sizing below
// NOTE: real ws size = 64 rows * 512 i * 1024 c = (BSZ*NH) * SEQ * DM
__device__ float g_ws_real[(BSZ*NH) * SEQ * DM]; // 134 MB  ((b*16+h)*512 + i)*1024 + c
__device__ float g_attn_out[NROWS * DM];      // 8 MB   (b*S+i, h*64+d)

// ---------------------------------------------------------------------------
// Generic SGEMM: C[M,N] = A[M,K] @ B[K,N], row-major, M%128==0, N%128==0, K%8==0
// ---------------------------------------------------------------------------
__global__ __launch_bounds__(256) void sgemm128(const float* __restrict__ A,
                                                const float* __restrict__ B,
                                                float* __restrict__ C,
                                                int M, int N, int K) {
    const int BM = 128, BN = 128, BK = 8, TM = 8, TN = 8;
    __shared__ float As[BK][BM];
    __shared__ float Bs[BK][BN];
    int bx = blockIdx.x, by = blockIdx.y;
    int tid = threadIdx.x;
    int trow = tid >> 4;       // 0..15
    int tcol = tid & 15;       // 0..15

    int arow = tid >> 1;                 // 0..127
    int acol = (tid & 1) * 4;            // 0 or 4
    int brow = tid >> 5;                 // 0..7
    int bcol = (tid & 31) * 4;           // 0..124

    const float* Ab = A + (long)(by * BM) * K;
    const float* Bb = B + bx * BN;

    float acc[TM][TN];
#pragma unroll
    for (int m = 0; m < TM; m++)
#pragma unroll
        for (int n = 0; n < TN; n++) acc[m][n] = 0.f;

    for (int k0 = 0; k0 < K; k0 += BK) {
        float4 av = *(const float4*)&Ab[(long)arow * K + k0 + acol];
        As[acol + 0][arow] = av.x;
        As[acol + 1][arow] = av.y;
        As[acol + 2][arow] = av.z;
        As[acol + 3][arow] = av.w;
        *(float4*)&Bs[brow][bcol] = *(const float4*)&Bb[(long)(k0 + brow) * N + bcol];
        __syncthreads();
#pragma unroll
        for (int kk = 0; kk < BK; kk++) {
            float4 a0 = *(const float4*)&As[kk][trow * TM];
            float4 a1 = *(const float4*)&As[kk][trow * TM + 4];
            float4 b0 = *(const float4*)&Bs[kk][tcol * TN];
            float4 b1 = *(const float4*)&Bs[kk][tcol * TN + 4];
            float af[TM] = {a0.x, a0.y, a0.z, a0.w, a1.x, a1.y, a1.z, a1.w};
            float bf[TN] = {b0.x, b0.y, b0.z, b0.w, b1.x, b1.y, b1.z, b1.w};
#pragma unroll
            for (int m = 0; m < TM; m++)
#pragma unroll
                for (int n = 0; n < TN; n++) acc[m][n] += af[m] * bf[n];
        }
        __syncthreads();
    }

#pragma unroll
    for (int m = 0; m < TM; m++) {
        int row = by * BM + trow * TM + m;
#pragma unroll
        for (int n = 0; n < TN; n += 4) {
            float4 v = make_float4(acc[m][n], acc[m][n + 1], acc[m][n + 2], acc[m][n + 3]);
            *(float4*)&C[(long)row * N + bx * BN + tcol * TN + n] = v;
        }
    }
}

// ---------------------------------------------------------------------------
// RoPE in-place: t has shape [NROWS, nheads, 64]; pos = row % SEQ
// ---------------------------------------------------------------------------
__global__ void rope_kernel(float* __restrict__ t,
                            const float* __restrict__ cs,
                            const float* __restrict__ sn,
                            int nheads, int total_pairs) {
    int idx = blockIdx.x * blockDim.x + threadIdx.x;
    if (idx >= total_pairs) return;
    int p = idx & 31;                 // pair index within head (32 pairs)
    int h = (idx >> 5) % nheads;
    int row = idx / (32 * nheads);
    int pos = row & (SEQ - 1);
    float c = cs[pos * 32 + p];
    float s = sn[pos * 32 + p];
    float* base = t + ((long)row * nheads + h) * HD + 2 * p;
    float r = base[0], im = base[1];
    base[0] = r * c - im * s;
    base[1] = r * s + im * c;
}

// ---------------------------------------------------------------------------
// Transpose K: (b*S+j, kv*64+d) -> (b,kv,d,j)
// ---------------------------------------------------------------------------
__global__ void transpose_k(const float* __restrict__ xk, float* __restrict__ xkT) {
    int idx = blockIdx.x * blockDim.x + threadIdx.x;
    if (idx >= BSZ * NKV * HD * SEQ) return;
    int j = idx & 511;
    int d = (idx >> 9) & 63;
    int kv = (idx >> 15) & 3;
    int b = idx >> 17;
    xkT[idx] = xk[((long)(b * SEQ + j)) * (NKV * HD) + kv * HD + d];
}

// ---------------------------------------------------------------------------
// Scores + causal softmax -> attn[(b*16+h)*512 + i][512]
// grid (SEQ, NH, BSZ), 256 threads
// ---------------------------------------------------------------------------
__global__ __launch_bounds__(256) void scores_softmax(const float* __restrict__ xq,
                                                      const float* __restrict__ xkT,
                                                      float* __restrict__ attn) {
    int i = blockIdx.x, h = blockIdx.y, b = blockIdx.z;
    int kv = h >> 2;
    int tid = threadIdx.x;
    __shared__ float qs[HD];
    __shared__ float red[256];
    if (tid < HD) qs[tid] = xq[((long)(b * SEQ + i)) * DM + h * HD + tid];
    __syncthreads();

    int nj = i + 1;
    const float* kT = xkT + ((long)(b * NKV + kv)) * HD * SEQ;
    float sc[2];
#pragma unroll
    for (int t = 0; t < 2; t++) {
        int j = tid + t * 256;
        float acc = -INFINITY;
        if (j < nj) {
            acc = 0.f;
#pragma unroll
            for (int d = 0; d < HD; d++) acc += qs[d] * kT[d * SEQ + j];
            acc *= 0.125f;  // 1/sqrt(64)
        }
        sc[t] = acc;
    }
    // max reduction
    float m = fmaxf(sc[0], sc[1]);
    red[tid] = m;
    __syncthreads();
    for (int s2 = 128; s2 > 0; s2 >>= 1) {
        if (tid < s2) red[tid] = fmaxf(red[tid], red[tid + s2]);
        __syncthreads();
    }
    m = red[0];
    __syncthreads();
    float e[2];
#pragma unroll
    for (int t = 0; t < 2; t++) {
        int j = tid + t * 256;
        e[t] = (j < nj) ? expf(sc[t] - m) : 0.f;
    }
    red[tid] = e[0] + e[1];
    __syncthreads();
    for (int s2 = 128; s2 > 0; s2 >>= 1) {
        if (tid < s2) red[tid] += red[tid + s2];
        __syncthreads();
    }
    float inv = 1.0f / red[0];
    float* arow = attn + ((long)((b * NH + h) * SEQ + i)) * SEQ;
#pragma unroll
    for (int t = 0; t < 2; t++) {
        int j = tid + t * 256;
        arow[j] = e[t] * inv;
    }
}

// ---------------------------------------------------------------------------
// ws GEMM (batched over i): C_i[64,1024] = A_i[64, K=i+1] @ symbols[i][K,1024]
// A_i[row,j] = attn[(row*512 + i)*512 + j], row = b*16+h
// grid (8 n-tiles, 512 i), 256 threads. BM=64, BN=128, BK=16, TM=4, TN=8.
// attn[j>i]==0 exactly, so K rounds up to BK without guards.
// ---------------------------------------------------------------------------
__global__ __launch_bounds__(256) void ws_gemm(const float* __restrict__ attn,
                                               const float* __restrict__ symbols,
                                               float* __restrict__ ws) {
    const int BM = 64, BN = 128, BK = 16, TM = 4, TN = 8;
    __shared__ float As[BK][BM];
    __shared__ float Bs[BK][BN];
    int i = blockIdx.y;
    int nbase = blockIdx.x * BN;
    int tid = threadIdx.x;
    int trow = tid >> 4;   // 0..15 -> rows trow*4
    int tcol = tid & 15;   // 0..15 -> cols tcol*8

    int arow = tid >> 2;              // 0..63
    int acol = (tid & 3) * 4;         // 0..12
    int brow = tid >> 5;              // 0..7 (loads rows brow and brow+8)
    int bcol = (tid & 31) * 4;        // 0..124

    int nj = i + 1;
    int kmax = (nj + BK - 1) & ~(BK - 1);   // <= 512

    const float* Abase = attn + (long)i * SEQ;          // + row*512*512 + j
    const float* Bbase = symbols + (long)i * SEQ * DM + nbase;

    float acc[TM][TN];
#pragma unroll
    for (int m = 0; m < TM; m++)
#pragma unroll
        for (int n = 0; n < TN; n++) acc[m][n] = 0.f;

    for (int k0 = 0; k0 < kmax; k0 += BK) {
        float4 av = *(const float4*)&Abase[(long)arow * (SEQ * SEQ) + k0 + acol];
        As[acol + 0][arow] = av.x;
        As[acol + 1][arow] = av.y;
        As[acol + 2][arow] = av.z;
        As[acol + 3][arow] = av.w;
        *(float4*)&Bs[brow][bcol]     = *(const float4*)&Bbase[(long)(k0 + brow) * DM + bcol];
        *(float4*)&Bs[brow + 8][bcol] = *(const float4*)&Bbase[(long)(k0 + brow + 8) * DM + bcol];
        __syncthreads();
#pragma unroll
        for (int kk = 0; kk < BK; kk++) {
            float4 a0 = *(const float4*)&As[kk][trow * TM];
            float4 b0 = *(const float4*)&Bs[kk][tcol * TN];
            float4 b1 = *(const float4*)&Bs[kk][tcol * TN + 4];
            float af[TM] = {a0.x, a0.y, a0.z, a0.w};
            float bf[TN] = {b0.x, b0.y, b0.z, b0.w, b1.x, b1.y, b1.z, b1.w};
#pragma unroll
            for (int m = 0; m < TM; m++)
#pragma unroll
                for (int n = 0; n < TN; n++) acc[m][n] += af[m] * bf[n];
        }
        __syncthreads();
    }

#pragma unroll
    for (int m = 0; m < TM; m++) {
        int row = trow * TM + m;          // b*16+h
        float* crow = ws + ((long)row * SEQ + i) * DM + nbase + tcol * TN;
#pragma unroll
        for (int n = 0; n < TN; n += 4) {
            float4 v = make_float4(acc[m][n], acc[m][n + 1], acc[m][n + 2], acc[m][n + 3]);
            *(float4*)&crow[n] = v;
        }
    }
}

// ---------------------------------------------------------------------------
// wv apply: out_pre[b*S+i, h*64+d] = sum_c ws[(b*16+h)*512+i, c] * wv[c, kv*64+d]
// grid (NROWS), 256 threads: h = tid/16, dq = tid%16 (4 d's each)
// ---------------------------------------------------------------------------
__global__ __launch_bounds__(256) void wv_apply(const float* __restrict__ ws,
                                                const float* __restrict__ wv,
                                                float* __restrict__ outp) {
    int bi = blockIdx.x;
    int b = bi >> 9;
    int i = bi & 511;
    int tid = threadIdx.x;
    int h = tid >> 4;
    int dq = tid & 15;
    int kv = h >> 2;
    const float* wsrow = ws + ((long)(b * NH + h) * SEQ + i) * DM;
    const float* wvp = wv + kv * HD + dq * 4;
    float4 acc = make_float4(0.f, 0.f, 0.f, 0.f);
#pragma unroll 8
    for (int c = 0; c < DM; c++) {
        float w = __ldg(&wsrow[c]);
        float4 v = *(const float4*)&wvp[(long)c * (NKV * HD)];
        acc.x += w * v.x;
        acc.y += w * v.y;
        acc.z += w * v.z;
        acc.w += w * v.w;
    }
    *(float4*)&outp[(long)bi * DM + h * HD + dq * 4] = acc;
}

// ---------------------------------------------------------------------------
extern "C" void kernel_launch(void* const* d_in, const int* in_sizes, int n_in,
                              void* d_out, int out_size) {
    const float* x       = (const float*)d_in[0];
    const float* symbols = (const float*)d_in[1];
    const float* fcos    = (const float*)d_in[2];
    const float* fsin    = (const float*)d_in[3];
    const float* wq      = (const float*)d_in[4];
    const float* wk      = (const float*)d_in[5];
    const float* wv      = (const float*)d_in[6];
    const float* wo      = (const float*)d_in[7];

    float* out  = (float*)d_out;                 // (4,512,1024)
    float* attn = out + OUT_ELEMS;               // (4,16,512,512)

    float *p_xq, *p_xk, *p_xkT, *p_ws, *p_ao;
    cudaGetSymbolAddress((void**)&p_xq, g_xq);
    cudaGetSymbolAddress((void**)&p_xk, g_xk);
    cudaGetSymbolAddress((void**)&p_xkT, g_xkT);
    cudaGetSymbolAddress((void**)&p_ws, g_ws_real);
    cudaGetSymbolAddress((void**)&p_ao, g_attn_out);

    // 1) Q/K projections
    sgemm128<<<dim3(DM / 128, NROWS / 128), 256>>>(x, wq, p_xq, NROWS, DM, DM);
    sgemm128<<<dim3((NKV * HD) / 128, NROWS / 128), 256>>>(x, wk, p_xk, NROWS, NKV * HD, DM);

    // 2) RoPE
    {
        int tp_q = NROWS * NH * 32;
        rope_kernel<<<(tp_q + 255) / 256, 256>>>(p_xq, fcos, fsin, NH, tp_q);
        int tp_k = NROWS * NKV * 32;
        rope_kernel<<<(tp_k + 255) / 256, 256>>>(p_xk, fcos, fsin, NKV, tp_k);
    }

    // 3) Transpose K for coalesced score loads
    transpose_k<<<(BSZ * NKV * HD * SEQ + 255) / 256, 256>>>(p_xk, p_xkT);

    // 4) Scores + causal softmax -> attn (second output region, also GEMM input)
    scores_softmax<<<dim3(SEQ, NH, BSZ), 256>>>(p_xq, p_xkT, attn);

    // 5) ws = attn @ symbols[i]  (batched over i; symbols read once, causal-truncated)
    ws_gemm<<<dim3(DM / 128, SEQ), 256>>>(attn, symbols, p_ws);

    // 6) out_pre = ws @ wv (per-kv slice)
    wv_apply<<<NROWS, 256>>>(p_ws, wv, p_ao);

    // 7) out = out_pre @ wo
    sgemm128<<<dim3(DM / 128, NROWS / 128), 256>>>(p_ao, wo, out, NROWS, DM, DM);
}